// round 3
// baseline (speedup 1.0000x reference)
#include <cuda_runtime.h>
#include <cuda_bf16.h>

// Inputs (metadata order):
//  0 embed  [N,64] f32          (N=1500 -> 96000 elems)
//  1 edge_index [2,E] int       (E=65536 -> 131072 elems; int32 OR int64, sniffed)
//  2 noise  [N*N] f32
//  3 tmp    [1] f32  (temperature beta)
//  4 W1     [128,64] f32
//  5 b1     [64] f32
//  6 W2     [64,1] f32
//  7 b2     [1] f32
// Output: edge_mask [E] f32

#define MAXN 1500

// Scratch: per node n, row of 128 floats: [0:64) = h1[n]+b1, [64:128) = h2[n]
__device__ float g_h[MAXN * 128];
__device__ int   g_is64;   // 1 if edge_index words look like little-endian int64

// ---------------------------------------------------------------------------
// Kernel 0: dtype sniff. If edge_index really is int64 (values < 2^31, nonneg),
// every odd 32-bit word is zero. With int32 data these words are random node
// indices in [0,1500) -> OR over 256 of them is ~never zero.
// ---------------------------------------------------------------------------
__global__ void detect_dtype(const int* __restrict__ w, int nwords)
{
    if (threadIdx.x == 0 && blockIdx.x == 0) {
        int acc = 0;
        int lim = (nwords < 512) ? nwords : 512;
        for (int k = 1; k < lim; k += 2) acc |= w[k];
        g_is64 = (acc == 0) ? 1 : 0;
    }
}

// ---------------------------------------------------------------------------
// Kernel 1: h1 = embed @ W1[:64] + b1 ; h2 = embed @ W1[64:]
// One block per node, 128 threads (t<64 -> h1 column k=t, t>=64 -> h2 column).
// ---------------------------------------------------------------------------
__global__ void __launch_bounds__(128) precompute_h(
    const float* __restrict__ embed,
    const float* __restrict__ W1,
    const float* __restrict__ b1,
    int N)
{
    __shared__ float se[64];
    int n = blockIdx.x;
    int t = threadIdx.x;          // 0..127
    if (t < 64) se[t] = embed[n * 64 + t];
    __syncthreads();

    int half = t >> 6;            // 0 -> h1, 1 -> h2
    int k    = t & 63;
    const float* w = W1 + (half * 64) * 64 + k;   // W1[(half*64 + f)][k]
    float s = 0.0f;
#pragma unroll
    for (int f = 0; f < 64; f++)
        s = fmaf(se[f], w[f * 64], s);
    if (half == 0) s += b1[k];
    g_h[n * 128 + t] = s;
}

// ---------------------------------------------------------------------------
// Kernel 2: one warp per edge.
// log_alpha[i,j] = sum_k relu(h1[i,k] + h2[j,k]) * W2[k] + b2
// gate(x, nz)    = sigmoid((log nz - log1p(-nz) + x) / beta)
// out[e] = 0.5 * (gate(la_ij, noise[i*N+j]) + gate(la_ji, noise[j*N+i]))
// ---------------------------------------------------------------------------
__global__ void __launch_bounds__(256) edge_gate(
    const void* __restrict__ ei_raw,
    const float* __restrict__ noise,
    const float* __restrict__ tmpp,
    const float* __restrict__ W2,
    const float* __restrict__ b2,
    float* __restrict__ out,
    int N, int E)
{
    int gtid = blockIdx.x * blockDim.x + threadIdx.x;
    int warp = gtid >> 5;
    int lane = threadIdx.x & 31;
    if (warp >= E) return;

    int i, j;
    if (g_is64) {
        const long long* e64 = (const long long*)ei_raw;
        i = (int)e64[warp];
        j = (int)e64[E + warp];
    } else {
        const int* e32 = (const int*)ei_raw;
        i = e32[warp];
        j = e32[E + warp];
    }
    // clamp defensively: a wrong dtype guess becomes a rel_err, not a trap
    i = min(max(i, 0), N - 1);
    j = min(max(j, 0), N - 1);

    const float* hi = g_h + i * 128;
    const float* hj = g_h + j * 128;

    float w0 = W2[lane];
    float w1 = W2[lane + 32];

    // row i: h1 at [0:64), h2 at [64:128); same for row j
    float h1i0 = hi[lane],      h1i1 = hi[lane + 32];
    float h2i0 = hi[lane + 64], h2i1 = hi[lane + 96];
    float h1j0 = hj[lane],      h1j1 = hj[lane + 32];
    float h2j0 = hj[lane + 64], h2j1 = hj[lane + 96];

    float sij = fmaxf(h1i0 + h2j0, 0.0f) * w0 + fmaxf(h1i1 + h2j1, 0.0f) * w1;
    float sji = fmaxf(h1j0 + h2i0, 0.0f) * w0 + fmaxf(h1j1 + h2i1, 0.0f) * w1;

#pragma unroll
    for (int off = 16; off; off >>= 1) {
        sij += __shfl_xor_sync(0xffffffffu, sij, off);
        sji += __shfl_xor_sync(0xffffffffu, sji, off);
    }

    if (lane == 0) {
        float beta = tmpp[0];
        float bb   = b2[0];
        float inv_beta = 1.0f / beta;

        float nij = noise[i * N + j];
        float nji = noise[j * N + i];

        float xij = (logf(nij) - log1pf(-nij) + sij + bb) * inv_beta;
        float xji = (logf(nji) - log1pf(-nji) + sji + bb) * inv_beta;

        float gij = 1.0f / (1.0f + expf(-xij));
        float gji = 1.0f / (1.0f + expf(-xji));

        out[warp] = 0.5f * (gij + gji);
    }
}

// ---------------------------------------------------------------------------
extern "C" void kernel_launch(void* const* d_in, const int* in_sizes, int n_in,
                              void* d_out, int out_size)
{
    const float* embed = (const float*)d_in[0];
    const void*  ei    = d_in[1];
    const float* noise = (const float*)d_in[2];
    const float* tmp   = (const float*)d_in[3];
    const float* W1    = (const float*)d_in[4];
    const float* b1    = (const float*)d_in[5];
    const float* W2    = (const float*)d_in[6];
    const float* b2    = (const float*)d_in[7];
    float*       out   = (float*)d_out;

    int N = in_sizes[0] / 64;      // 1500
    int E = in_sizes[1] / 2;       // 65536

    detect_dtype<<<1, 32>>>((const int*)ei, in_sizes[1] * 2);
    precompute_h<<<N, 128>>>(embed, W1, b1, N);

    int threads = 256;             // 8 warps per block, one warp per edge
    int blocks  = (E * 32 + threads - 1) / threads;
    edge_gate<<<blocks, threads>>>(ei, noise, tmp, W2, b2, out, N, E);
}

// round 4
// speedup vs baseline: 1.1681x; 1.1681x over previous
#include <cuda_runtime.h>
#include <cuda_bf16.h>

// Inputs (metadata order):
//  0 embed  [N,64] f32          (N=1500)
//  1 edge_index [2,E]           (E=65536; int32 OR int64, sniffed on device)
//  2 noise  [N*N] f32
//  3 tmp    [1] f32  (temperature beta)
//  4 W1     [128,64] f32
//  5 b1     [64] f32
//  6 W2     [64,1] f32
//  7 b2     [1] f32
// Output: edge_mask [E] f32

#define MAXN 1500

// Scratch: per node n, row of 128 floats: [0:64) = h1[n]+b1, [64:128) = h2[n]
__device__ float g_h[MAXN * 128];
__device__ int   g_is64;   // 1 if edge_index words look like little-endian int64

// ---------------------------------------------------------------------------
// Kernel 1: h1 = embed @ W1[:64] + b1 ; h2 = embed @ W1[64:]
// One block per node, 128 threads. Block N additionally does the dtype sniff
// in parallel (128 odd words, OR-reduced via ballot) — no serial detector.
// ---------------------------------------------------------------------------
__global__ void __launch_bounds__(128) precompute_h(
    const float* __restrict__ embed,
    const float* __restrict__ W1,
    const float* __restrict__ b1,
    const int*  __restrict__ eiw,   // edge_index viewed as 32-bit words
    int nwords,
    int N)
{
    int n = blockIdx.x;
    int t = threadIdx.x;          // 0..127

    if (n == N) {
        // dtype sniff: genuine int64 (values < 2^31) -> all odd words zero.
        // int32 data -> odd words are random node indices, OR != 0 w.h.p.
        __shared__ int s_nz[4];
        int k = 2 * t + 1;        // odd word index, t in [0,128)
        int v = (k < nwords) ? eiw[k] : 0;
        unsigned nz = __ballot_sync(0xffffffffu, v != 0);
        if ((t & 31) == 0) s_nz[t >> 5] = (nz != 0);
        __syncthreads();
        if (t == 0)
            g_is64 = (s_nz[0] | s_nz[1] | s_nz[2] | s_nz[3]) ? 0 : 1;
        return;
    }

    __shared__ float se[64];
    if (t < 64) se[t] = embed[n * 64 + t];
    __syncthreads();

    int half = t >> 6;            // 0 -> h1, 1 -> h2
    int k    = t & 63;
    const float* w = W1 + (half * 64) * 64 + k;   // W1[(half*64 + f)][k]
    float s = 0.0f;
#pragma unroll
    for (int f = 0; f < 64; f++)
        s = fmaf(se[f], w[f * 64], s);
    if (half == 0) s += b1[k];
    g_h[n * 128 + t] = s;
}

// ---------------------------------------------------------------------------
// Kernel 2: one warp per edge.
// log_alpha[i,j] = sum_k relu(h1[i,k] + h2[j,k]) * W2[k] + b2
// gate(x, nz)    = sigmoid((log nz - log1p(-nz) + x) / beta)
// out[e] = 0.5 * (gate(la_ij, noise[i*N+j]) + gate(la_ji, noise[j*N+i]))
// ---------------------------------------------------------------------------
__global__ void __launch_bounds__(256) edge_gate(
    const void* __restrict__ ei_raw,
    const float* __restrict__ noise,
    const float* __restrict__ tmpp,
    const float* __restrict__ W2,
    const float* __restrict__ b2,
    float* __restrict__ out,
    int N, int E)
{
    int gtid = blockIdx.x * blockDim.x + threadIdx.x;
    int warp = gtid >> 5;
    int lane = threadIdx.x & 31;
    if (warp >= E) return;

    int i, j;
    if (g_is64) {
        const long long* e64 = (const long long*)ei_raw;
        i = (int)e64[warp];
        j = (int)e64[E + warp];
    } else {
        const int* e32 = (const int*)ei_raw;
        i = e32[warp];
        j = e32[E + warp];
    }
    // clamp defensively: a wrong dtype guess becomes a rel_err, not a trap
    i = min(max(i, 0), N - 1);
    j = min(max(j, 0), N - 1);

    // Hoist the scattered DRAM noise loads so their latency overlaps the
    // L2-resident h-row loads below (lanes 0/1 issue one each).
    float nz = 0.0f;
    if (lane == 0) nz = noise[i * N + j];
    if (lane == 1) nz = noise[j * N + i];

    const float* hi = g_h + i * 128;
    const float* hj = g_h + j * 128;

    float w0 = W2[lane];
    float w1 = W2[lane + 32];

    float h1i0 = hi[lane],      h1i1 = hi[lane + 32];
    float h2i0 = hi[lane + 64], h2i1 = hi[lane + 96];
    float h1j0 = hj[lane],      h1j1 = hj[lane + 32];
    float h2j0 = hj[lane + 64], h2j1 = hj[lane + 96];

    float sij = fmaxf(h1i0 + h2j0, 0.0f) * w0 + fmaxf(h1i1 + h2j1, 0.0f) * w1;
    float sji = fmaxf(h1j0 + h2i0, 0.0f) * w0 + fmaxf(h1j1 + h2i1, 0.0f) * w1;

#pragma unroll
    for (int off = 16; off; off >>= 1) {
        sij += __shfl_xor_sync(0xffffffffu, sij, off);
        sji += __shfl_xor_sync(0xffffffffu, sji, off);
    }

    float nji = __shfl_sync(0xffffffffu, nz, 1);

    if (lane == 0) {
        float beta = tmpp[0];
        float bb   = b2[0];
        float inv_beta = 1.0f / beta;

        float nij = nz;

        float xij = (logf(nij) - log1pf(-nij) + sij + bb) * inv_beta;
        float xji = (logf(nji) - log1pf(-nji) + sji + bb) * inv_beta;

        float gij = 1.0f / (1.0f + expf(-xij));
        float gji = 1.0f / (1.0f + expf(-xji));

        out[warp] = 0.5f * (gij + gji);
    }
}

// ---------------------------------------------------------------------------
extern "C" void kernel_launch(void* const* d_in, const int* in_sizes, int n_in,
                              void* d_out, int out_size)
{
    const float* embed = (const float*)d_in[0];
    const void*  ei    = d_in[1];
    const float* noise = (const float*)d_in[2];
    const float* tmp   = (const float*)d_in[3];
    const float* W1    = (const float*)d_in[4];
    const float* b1    = (const float*)d_in[5];
    const float* W2    = (const float*)d_in[6];
    const float* b2    = (const float*)d_in[7];
    float*       out   = (float*)d_out;

    int N = in_sizes[0] / 64;      // 1500
    int E = in_sizes[1] / 2;       // 65536

    // N compute blocks + 1 sniff block
    precompute_h<<<N + 1, 128>>>(embed, W1, b1, (const int*)ei,
                                 in_sizes[1] * 2, N);

    int threads = 256;             // 8 warps per block, one warp per edge
    int blocks  = (E * 32 + threads - 1) / threads;
    edge_gate<<<blocks, threads>>>(ei, noise, tmp, W2, b2, out, N, E);
}

// round 5
// speedup vs baseline: 1.6661x; 1.4264x over previous
#include <cuda_runtime.h>
#include <cuda_bf16.h>

// Inputs (metadata order):
//  0 embed  [N,64] f32          (N=1500)
//  1 edge_index [2,E]           (E=65536; int32 OR int64, sniffed on device)
//  2 noise  [N*N] f32
//  3 tmp    [1] f32  (temperature beta)
//  4 W1     [128,64] f32
//  5 b1     [64] f32
//  6 W2     [64,1] f32
//  7 b2     [1] f32
// Output: edge_mask [E] f32

#define MAXN 1500

// Scratch: per node n, row of 128 floats: [0:64) = h1[n]+b1, [64:128) = h2[n]
__device__ float g_h[MAXN * 128];
__device__ int   g_is64;   // 1 if edge_index words look like little-endian int64

// ---------------------------------------------------------------------------
// Kernel 1: h1 = embed @ W1[:64] + b1 ; h2 = embed @ W1[64:]
// One block per node, 128 threads. Block N additionally does the dtype sniff.
// ---------------------------------------------------------------------------
__global__ void __launch_bounds__(128) precompute_h(
    const float* __restrict__ embed,
    const float* __restrict__ W1,
    const float* __restrict__ b1,
    const int*  __restrict__ eiw,   // edge_index viewed as 32-bit words
    int nwords,
    int N)
{
    int n = blockIdx.x;
    int t = threadIdx.x;          // 0..127

    if (n == N) {
        // dtype sniff: genuine int64 (values < 2^31) -> all odd words zero.
        __shared__ int s_nz[4];
        int k = 2 * t + 1;
        int v = (k < nwords) ? eiw[k] : 0;
        unsigned nz = __ballot_sync(0xffffffffu, v != 0);
        if ((t & 31) == 0) s_nz[t >> 5] = (nz != 0);
        __syncthreads();
        if (t == 0)
            g_is64 = (s_nz[0] | s_nz[1] | s_nz[2] | s_nz[3]) ? 0 : 1;
        return;
    }

    __shared__ float se[64];
    if (t < 64) se[t] = embed[n * 64 + t];
    __syncthreads();

    int half = t >> 6;            // 0 -> h1, 1 -> h2
    int k    = t & 63;
    const float* w = W1 + (half * 64) * 64 + k;   // W1[(half*64 + f)][k]
    float s = 0.0f;
#pragma unroll
    for (int f = 0; f < 64; f++)
        s = fmaf(se[f], w[f * 64], s);
    if (half == 0) s += b1[k];
    g_h[n * 128 + t] = s;
}

// ---------------------------------------------------------------------------
// Kernel 2: 256 threads = 8 warps = 8 edges per block.
// Phase 1 (warp per edge): lanes 0-15 reduce s_ij, lanes 16-31 reduce s_ji,
//   via float4 loads of the two 512B h-rows. Results + noise go to smem.
// Phase 2 (threads 0-15): all 16 gate evaluations of the block in parallel.
// ---------------------------------------------------------------------------
__global__ void __launch_bounds__(256) edge_gate(
    const void* __restrict__ ei_raw,
    const float* __restrict__ noise,
    const float* __restrict__ tmpp,
    const float* __restrict__ W2,
    const float* __restrict__ b2,
    float* __restrict__ out,
    int N, int E)
{
    __shared__ float s_s[16];    // [warp*2 + dir] log_alpha partial sums
    __shared__ float s_n[16];    // matching noise values

    int tid  = threadIdx.x;
    int wid  = tid >> 5;
    int lane = tid & 31;
    int edge = blockIdx.x * 8 + wid;
    bool active = edge < E;

    if (active) {
        int i, j;
        if (g_is64) {
            const long long* e64 = (const long long*)ei_raw;
            i = (int)e64[edge];
            j = (int)e64[E + edge];
        } else {
            const int* e32 = (const int*)ei_raw;
            i = e32[edge];
            j = e32[E + edge];
        }
        i = min(max(i, 0), N - 1);
        j = min(max(j, 0), N - 1);

        int  m   = lane & 15;
        bool top = lane >= 16;           // bottom: (i,j) dir; top: (j,i) dir

        // scattered noise load, issued early (one predicated LDG per warp-half)
        float nz = 0.0f;
        if (m == 0) nz = noise[top ? (j * N + i) : (i * N + j)];

        // h1 source = first node of this direction, h2 source = second
        const float4* A = (const float4*)(g_h + (top ? j : i) * 128);
        const float4* B = (const float4*)(g_h + (top ? i : j) * 128);
        float4 a = A[m];                 // h1[dir0][4m..4m+3]
        float4 b = B[16 + m];            // h2[dir1][4m..4m+3]
        float4 w = ((const float4*)W2)[m];

        float s;
        s  = fmaxf(a.x + b.x, 0.0f) * w.x;
        s += fmaxf(a.y + b.y, 0.0f) * w.y;
        s += fmaxf(a.z + b.z, 0.0f) * w.z;
        s += fmaxf(a.w + b.w, 0.0f) * w.w;

#pragma unroll
        for (int off = 8; off; off >>= 1)
            s += __shfl_xor_sync(0xffffffffu, s, off);

        if (m == 0) {                    // lane 0 and lane 16
            int slot = wid * 2 + (top ? 1 : 0);
            s_s[slot] = s;
            s_n[slot] = nz;
        }
    }

    __syncthreads();

    if (tid < 16) {
        int e = blockIdx.x * 8 + (tid >> 1);
        float s  = s_s[tid];
        float nz = s_n[tid];
        float inv_beta = 1.0f / tmpp[0];
        float x = (__logf(nz) - __logf(1.0f - nz) + s + b2[0]) * inv_beta;
        float g = 1.0f / (1.0f + __expf(-x));
        float go = __shfl_xor_sync(0x0000ffffu, g, 1);
        if ((tid & 1) == 0 && e < E)
            out[e] = 0.5f * (g + go);
    }
}

// ---------------------------------------------------------------------------
extern "C" void kernel_launch(void* const* d_in, const int* in_sizes, int n_in,
                              void* d_out, int out_size)
{
    const float* embed = (const float*)d_in[0];
    const void*  ei    = d_in[1];
    const float* noise = (const float*)d_in[2];
    const float* tmp   = (const float*)d_in[3];
    const float* W1    = (const float*)d_in[4];
    const float* b1    = (const float*)d_in[5];
    const float* W2    = (const float*)d_in[6];
    const float* b2    = (const float*)d_in[7];
    float*       out   = (float*)d_out;

    int N = in_sizes[0] / 64;      // 1500
    int E = in_sizes[1] / 2;       // 65536

    precompute_h<<<N + 1, 128>>>(embed, W1, b1, (const int*)ei,
                                 in_sizes[1] * 2, N);

    int blocks = (E + 7) / 8;      // 8 edges per 256-thread block
    edge_gate<<<blocks, 256>>>(ei, noise, tmp, W2, b2, out, N, E);
}

// round 6
// speedup vs baseline: 1.8930x; 1.1362x over previous
#include <cuda_runtime.h>
#include <cuda_bf16.h>

// Inputs (metadata order):
//  0 embed  [N,64] f32          (N=1500)
//  1 edge_index [2,E]           (E=65536; int32 OR int64, sniffed on device)
//  2 noise  [N*N] f32
//  3 tmp    [1] f32  (temperature beta)
//  4 W1     [128,64] f32
//  5 b1     [64] f32
//  6 W2     [64,1] f32
//  7 b2     [1] f32
// Output: edge_mask [E] f32

#define MAXN 1500

// Scratch: per node n, row of 128 floats: [0:64) = h1[n]+b1, [64:128) = h2[n]
__device__ float g_h[MAXN * 128];
__device__ int   g_is64;   // 1 if edge_index words look like little-endian int64

// ---------------------------------------------------------------------------
// Kernel 1: h1 = embed @ W1[:64] + b1 ; h2 = embed @ W1[64:]
// One block per node, 128 threads. Block N additionally does the dtype sniff.
// ---------------------------------------------------------------------------
__global__ void __launch_bounds__(128) precompute_h(
    const float* __restrict__ embed,
    const float* __restrict__ W1,
    const float* __restrict__ b1,
    const int*  __restrict__ eiw,   // edge_index viewed as 32-bit words
    int nwords,
    int N)
{
    int n = blockIdx.x;
    int t = threadIdx.x;          // 0..127

    if (n == N) {
        // dtype sniff: genuine int64 (values < 2^31) -> all odd words zero.
        __shared__ int s_nz[4];
        int k = 2 * t + 1;
        int v = (k < nwords) ? eiw[k] : 0;
        unsigned nz = __ballot_sync(0xffffffffu, v != 0);
        if ((t & 31) == 0) s_nz[t >> 5] = (nz != 0);
        __syncthreads();
        if (t == 0)
            g_is64 = (s_nz[0] | s_nz[1] | s_nz[2] | s_nz[3]) ? 0 : 1;
        return;
    }

    __shared__ float se[64];
    if (t < 64) se[t] = embed[n * 64 + t];
    __syncthreads();

    int half = t >> 6;            // 0 -> h1, 1 -> h2
    int k    = t & 63;
    const float* w = W1 + (half * 64) * 64 + k;   // W1[(half*64 + f)][k]
    float s = 0.0f;
#pragma unroll
    for (int f = 0; f < 64; f++)
        s = fmaf(se[f], w[f * 64], s);
    if (half == 0) s += b1[k];
    g_h[n * 128 + t] = s;
}

// ---------------------------------------------------------------------------
// Kernel 2: 4 edges per warp, no block barriers.
//   lane layout: d = lane>>2 (direction 0..7 = 4 edges x 2 dirs), m = lane&3.
//   Each lane: 4 float4 loads each of h1-row, h2-row, W2 -> 16 relu-dot terms.
//   Reduce over the 4 lanes of a direction (2 shfls); m==0 lanes (8 of them)
//   evaluate the gate; pair-combine via shfl; 4 lanes store.
// ---------------------------------------------------------------------------
__global__ void __launch_bounds__(256) edge_gate(
    const void* __restrict__ ei_raw,
    const float* __restrict__ noise,
    const float* __restrict__ tmpp,
    const float* __restrict__ W2,
    const float* __restrict__ b2,
    float* __restrict__ out,
    int N, int E)
{
    int tid   = threadIdx.x;
    int lane  = tid & 31;
    int gwarp = (blockIdx.x * blockDim.x + tid) >> 5;

    int d   = lane >> 2;      // direction 0..7
    int m   = lane & 3;       // quarter of the 64-dot
    int el  = d >> 1;         // edge-local 0..3
    int top = d & 1;          // 0: (i,j), 1: (j,i)

    int e = gwarp * 4 + el;
    bool active = e < E;
    int eld = active ? e : (E > 0 ? E - 1 : 0);

    int i, j;
    if (g_is64) {
        const long long* e64 = (const long long*)ei_raw;
        i = (int)e64[eld];
        j = (int)e64[E + eld];
    } else {
        const int* e32 = (const int*)ei_raw;
        i = e32[eld];
        j = e32[E + eld];
    }
    i = min(max(i, 0), N - 1);
    j = min(max(j, 0), N - 1);

    // scattered noise load (DRAM) issued first so it overlaps the L2 h loads
    float nz = 0.0f;
    if (m == 0) nz = __ldg(noise + (top ? (j * N + i) : (i * N + j)));

    const float4* A = (const float4*)(g_h + (top ? j : i) * 128);       // h1
    const float4* B = (const float4*)(g_h + (top ? i : j) * 128) + 16;  // h2
    const float4* W = (const float4*)W2;

    float4 a0 = A[m],      a1 = A[m + 4],  a2 = A[m + 8],  a3 = A[m + 12];
    float4 c0 = B[m],      c1 = B[m + 4],  c2 = B[m + 8],  c3 = B[m + 12];
    float4 w0 = W[m],      w1 = W[m + 4],  w2 = W[m + 8],  w3 = W[m + 12];

    float s;
    s  = fmaxf(a0.x + c0.x, 0.0f) * w0.x;
    s += fmaxf(a0.y + c0.y, 0.0f) * w0.y;
    s += fmaxf(a0.z + c0.z, 0.0f) * w0.z;
    s += fmaxf(a0.w + c0.w, 0.0f) * w0.w;
    s += fmaxf(a1.x + c1.x, 0.0f) * w1.x;
    s += fmaxf(a1.y + c1.y, 0.0f) * w1.y;
    s += fmaxf(a1.z + c1.z, 0.0f) * w1.z;
    s += fmaxf(a1.w + c1.w, 0.0f) * w1.w;
    s += fmaxf(a2.x + c2.x, 0.0f) * w2.x;
    s += fmaxf(a2.y + c2.y, 0.0f) * w2.y;
    s += fmaxf(a2.z + c2.z, 0.0f) * w2.z;
    s += fmaxf(a2.w + c2.w, 0.0f) * w2.w;
    s += fmaxf(a3.x + c3.x, 0.0f) * w3.x;
    s += fmaxf(a3.y + c3.y, 0.0f) * w3.y;
    s += fmaxf(a3.z + c3.z, 0.0f) * w3.z;
    s += fmaxf(a3.w + c3.w, 0.0f) * w3.w;

    // reduce across the 4 lanes of this direction
    s += __shfl_xor_sync(0xffffffffu, s, 1);
    s += __shfl_xor_sync(0xffffffffu, s, 2);

    // gate on m==0 lanes (8 lanes, all 8 directions in one pass)
    float g = 0.0f;
    if (m == 0) {
        float inv_beta = 1.0f / tmpp[0];
        float x = (__logf(nz) - __logf(1.0f - nz) + s + b2[0]) * inv_beta;
        g = 1.0f / (1.0f + __expf(-x));
    }
    // combine the two directions of each edge: lane 8*el <- lane 8*el+4
    float go = __shfl_xor_sync(0xffffffffu, g, 4);
    if ((lane & 7) == 0 && active)
        out[e] = 0.5f * (g + go);
}

// ---------------------------------------------------------------------------
extern "C" void kernel_launch(void* const* d_in, const int* in_sizes, int n_in,
                              void* d_out, int out_size)
{
    const float* embed = (const float*)d_in[0];
    const void*  ei    = d_in[1];
    const float* noise = (const float*)d_in[2];
    const float* tmp   = (const float*)d_in[3];
    const float* W1    = (const float*)d_in[4];
    const float* b1    = (const float*)d_in[5];
    const float* W2    = (const float*)d_in[6];
    const float* b2    = (const float*)d_in[7];
    float*       out   = (float*)d_out;

    int N = in_sizes[0] / 64;      // 1500
    int E = in_sizes[1] / 2;       // 65536

    precompute_h<<<N + 1, 128>>>(embed, W1, b1, (const int*)ei,
                                 in_sizes[1] * 2, N);

    // 4 edges per warp, 8 warps per block -> 32 edges per block
    int blocks = (E + 31) / 32;
    edge_gate<<<blocks, 256>>>(ei, noise, tmp, W2, b2, out, N, E);
}